// round 3
// baseline (speedup 1.0000x reference)
#include <cuda_runtime.h>
#include <math.h>

#define BATCH 2
#define SEQ   2048
#define EMB   1024
#define NH    16
#define HD    64
#define NTOK  (BATCH*SEQ)   // 4096

// Scratch (allocation-free): QKV projections and attention output.
static __device__ float g_qkv[(size_t)NTOK * 3 * EMB];   // 50.3 MB
static __device__ float g_attn[(size_t)NTOK * EMB];      // 16.8 MB

// ---------------------------------------------------------------------------
// SGEMM + bias: C[M,N] = A[M,K] @ B[K,N] + bias[N]
// 128x128 tile, BK=16, 256 threads, 8x8 micro-tile.
// M,N multiples of 128; K multiple of 16 (true for all our shapes).
// ---------------------------------------------------------------------------
__global__ __launch_bounds__(256, 2)
void sgemm_bias_128x128(const float* __restrict__ A, const float* __restrict__ B,
                        const float* __restrict__ bias, float* __restrict__ C,
                        int M, int N, int K)
{
    __shared__ float As[16][132];   // [k][m], padded
    __shared__ float Bs[16][128];   // [k][n]

    const int tid   = threadIdx.x;
    const int mBase = blockIdx.y * 128;
    const int nBase = blockIdx.x * 128;
    const int ty    = tid >> 4;   // 0..15 -> rows
    const int tx    = tid & 15;   // 0..15 -> cols

    float acc[8][8];
#pragma unroll
    for (int i = 0; i < 8; i++)
#pragma unroll
        for (int j = 0; j < 8; j++) acc[i][j] = 0.f;

    const int aRow0 = tid >> 2;   // + 64*i
    const int aK4   = tid & 3;
    const int bRow0 = tid >> 5;   // + 8*i
    const int bC4   = tid & 31;

    for (int k0 = 0; k0 < K; k0 += 16) {
        // A tile 128x16 -> transposed into As[k][m]
#pragma unroll
        for (int i = 0; i < 2; i++) {
            int row = aRow0 + i * 64;
            float4 v = *(const float4*)(A + (size_t)(mBase + row) * K + k0 + aK4 * 4);
            As[aK4 * 4 + 0][row] = v.x;
            As[aK4 * 4 + 1][row] = v.y;
            As[aK4 * 4 + 2][row] = v.z;
            As[aK4 * 4 + 3][row] = v.w;
        }
        // B tile 16x128 direct
#pragma unroll
        for (int i = 0; i < 2; i++) {
            int row = bRow0 + i * 8;
            *(float4*)&Bs[row][bC4 * 4] =
                *(const float4*)(B + (size_t)(k0 + row) * N + nBase + bC4 * 4);
        }
        __syncthreads();

#pragma unroll
        for (int kk = 0; kk < 16; kk++) {
            float a[8], b[8];
            *(float4*)&a[0] = *(const float4*)&As[kk][ty * 8];
            *(float4*)&a[4] = *(const float4*)&As[kk][ty * 8 + 4];
            *(float4*)&b[0] = *(const float4*)&Bs[kk][tx * 8];
            *(float4*)&b[4] = *(const float4*)&Bs[kk][tx * 8 + 4];
#pragma unroll
            for (int i = 0; i < 8; i++)
#pragma unroll
                for (int j = 0; j < 8; j++)
                    acc[i][j] = fmaf(a[i], b[j], acc[i][j]);
        }
        __syncthreads();
    }

    float bv[8];
#pragma unroll
    for (int j = 0; j < 8; j++) bv[j] = bias[nBase + tx * 8 + j];
#pragma unroll
    for (int i = 0; i < 8; i++) {
        int m = mBase + ty * 8 + i;
        float4 o0, o1;
        o0.x = acc[i][0] + bv[0]; o0.y = acc[i][1] + bv[1];
        o0.z = acc[i][2] + bv[2]; o0.w = acc[i][3] + bv[3];
        o1.x = acc[i][4] + bv[4]; o1.y = acc[i][5] + bv[5];
        o1.z = acc[i][6] + bv[6]; o1.w = acc[i][7] + bv[7];
        *(float4*)(C + (size_t)m * N + nBase + tx * 8)     = o0;
        *(float4*)(C + (size_t)m * N + nBase + tx * 8 + 4) = o1;
    }
}

// ---------------------------------------------------------------------------
// Flash attention, fp32. One CTA = 128 queries x one (batch, head).
// Key/value tiles of 64. 128 threads: ty=tid&15 (rows, 8 each), tx=tid>>4
// (cols, 8 each) -> 8x8 micro-tile covering 128x64.
// smem (floats): Qs 64*132 | Ks 64*68 | Vs 64*64 | Ss 64*132 | stats 3*128
// ---------------------------------------------------------------------------
#define ATTN_SMEM_FLOATS (64*132 + 64*68 + 64*64 + 64*132 + 3*128)  // 25728
#define ATTN_SMEM_BYTES  (ATTN_SMEM_FLOATS * 4)                     // 102912

__global__ __launch_bounds__(128, 2)
void mha_attn_kernel(const float* __restrict__ qkv, float* __restrict__ out)
{
    extern __shared__ float smbuf[];
    float* Qs   = smbuf;               // [d][m]  64 x 132
    float* Ks   = Qs + 64 * 132;       // [d][n]  64 x 68
    float* Vs   = Ks + 64 * 68;        // [kv][d] 64 x 64
    float* Ss   = Vs + 64 * 64;        // [n][m]  64 x 132
    float* st_m = Ss + 64 * 132;       // [128]
    float* st_l = st_m + 128;          // [128]
    float* st_a = st_l + 128;          // [128]

    const int tid = threadIdx.x;
    const int ty  = tid & 15;          // row group (8 rows)
    const int tx  = tid >> 4;          // col group (8 cols), 0..7
    const int h   = blockIdx.y & (NH - 1);
    const int b   = blockIdx.y >> 4;
    const int q0  = blockIdx.x * 128;
    const size_t rs = 3 * EMB;

    const float* Qg = qkv + ((size_t)b * SEQ + q0) * rs + h * HD;
    const float* Kg = qkv + (size_t)b * SEQ * rs + EMB + h * HD;
    const float* Vg = qkv + (size_t)b * SEQ * rs + 2 * EMB + h * HD;

    // Load Q tile (128 x 64), fold in 1/sqrt(D) = 0.125, store d-major.
#pragma unroll
    for (int it = 0; it < 16; it++) {
        int f  = tid + it * 128;
        int m  = f >> 4;
        int d4 = f & 15;
        float4 v = *(const float4*)(Qg + (size_t)m * rs + d4 * 4);
        Qs[(d4 * 4 + 0) * 132 + m] = v.x * 0.125f;
        Qs[(d4 * 4 + 1) * 132 + m] = v.y * 0.125f;
        Qs[(d4 * 4 + 2) * 132 + m] = v.z * 0.125f;
        Qs[(d4 * 4 + 3) * 132 + m] = v.w * 0.125f;
    }
    st_m[tid] = -1e30f;
    st_l[tid] = 0.f;

    float o[8][8];
#pragma unroll
    for (int i = 0; i < 8; i++)
#pragma unroll
        for (int j = 0; j < 8; j++) o[i][j] = 0.f;

    __syncthreads();

    for (int kt = 0; kt < SEQ; kt += 64) {
        // Load K (d-major, transposed) and V (kv-major) tiles.
#pragma unroll
        for (int it = 0; it < 8; it++) {
            int f  = tid + it * 128;
            int n  = f >> 4;
            int d4 = f & 15;
            const float* kp = Kg + (size_t)(kt + n) * rs + d4 * 4;
            float4 kv = *(const float4*)kp;
            float4 vv = *(const float4*)(kp + EMB);   // V is +EMB past K
            Ks[(d4 * 4 + 0) * 68 + n] = kv.x;
            Ks[(d4 * 4 + 1) * 68 + n] = kv.y;
            Ks[(d4 * 4 + 2) * 68 + n] = kv.z;
            Ks[(d4 * 4 + 3) * 68 + n] = kv.w;
            *(float4*)&Vs[n * 64 + d4 * 4] = vv;
        }
        __syncthreads();

        // S = (Q*scale) @ K^T   (128 x 64)
        float s[8][8];
#pragma unroll
        for (int i = 0; i < 8; i++)
#pragma unroll
            for (int j = 0; j < 8; j++) s[i][j] = 0.f;

#pragma unroll 8
        for (int d = 0; d < 64; d++) {
            float a[8], bb[8];
            *(float4*)&a[0]  = *(const float4*)&Qs[d * 132 + ty * 8];
            *(float4*)&a[4]  = *(const float4*)&Qs[d * 132 + ty * 8 + 4];
            *(float4*)&bb[0] = *(const float4*)&Ks[d * 68 + tx * 8];
            *(float4*)&bb[4] = *(const float4*)&Ks[d * 68 + tx * 8 + 4];
#pragma unroll
            for (int i = 0; i < 8; i++)
#pragma unroll
                for (int j = 0; j < 8; j++)
                    s[i][j] = fmaf(a[i], bb[j], s[i][j]);
        }

        // Store S n-major (float4 along m) for the softmax + PV stages.
#pragma unroll
        for (int j = 0; j < 8; j++) {
            int n = tx * 8 + j;
            float4 v0 = make_float4(s[0][j], s[1][j], s[2][j], s[3][j]);
            float4 v1 = make_float4(s[4][j], s[5][j], s[6][j], s[7][j]);
            *(float4*)&Ss[n * 132 + ty * 8]     = v0;
            *(float4*)&Ss[n * 132 + ty * 8 + 4] = v1;
        }
        __syncthreads();

        // Online softmax: one thread per query row.
        {
            float mo = st_m[tid];
            float mx = mo;
#pragma unroll 8
            for (int n = 0; n < 64; n++)
                mx = fmaxf(mx, Ss[n * 132 + tid]);
            float alpha = __expf(mo - mx);
            float l = st_l[tid] * alpha;
#pragma unroll 8
            for (int n = 0; n < 64; n++) {
                float p = __expf(Ss[n * 132 + tid] - mx);
                Ss[n * 132 + tid] = p;
                l += p;
            }
            st_m[tid] = mx;
            st_l[tid] = l;
            st_a[tid] = alpha;
        }
        __syncthreads();

        // O = O*alpha + P @ V   (128 x 64)
        float al[8];
#pragma unroll
        for (int i = 0; i < 8; i++) al[i] = st_a[ty * 8 + i];
#pragma unroll
        for (int i = 0; i < 8; i++)
#pragma unroll
            for (int j = 0; j < 8; j++) o[i][j] *= al[i];

#pragma unroll 8
        for (int kv = 0; kv < 64; kv++) {
            float a[8], bb[8];
            *(float4*)&a[0]  = *(const float4*)&Ss[kv * 132 + ty * 8];
            *(float4*)&a[4]  = *(const float4*)&Ss[kv * 132 + ty * 8 + 4];
            *(float4*)&bb[0] = *(const float4*)&Vs[kv * 64 + tx * 8];
            *(float4*)&bb[4] = *(const float4*)&Vs[kv * 64 + tx * 8 + 4];
#pragma unroll
            for (int i = 0; i < 8; i++)
#pragma unroll
                for (int j = 0; j < 8; j++)
                    o[i][j] = fmaf(a[i], bb[j], o[i][j]);
        }
        __syncthreads();   // protect Ks/Vs/Ss before next tile's loads
    }

    // Finalize: divide by l, write to attn buffer [tok, h*64+d].
    float inv[8];
#pragma unroll
    for (int i = 0; i < 8; i++) inv[i] = 1.0f / st_l[ty * 8 + i];

    const size_t orow = (size_t)b * SEQ + q0;
#pragma unroll
    for (int i = 0; i < 8; i++) {
        int m = ty * 8 + i;
        float4 v0, v1;
        v0.x = o[i][0] * inv[i]; v0.y = o[i][1] * inv[i];
        v0.z = o[i][2] * inv[i]; v0.w = o[i][3] * inv[i];
        v1.x = o[i][4] * inv[i]; v1.y = o[i][5] * inv[i];
        v1.z = o[i][6] * inv[i]; v1.w = o[i][7] * inv[i];
        float* dst = out + (orow + m) * EMB + h * HD + tx * 8;
        *(float4*)dst       = v0;
        *(float4*)(dst + 4) = v1;
    }
}

// ---------------------------------------------------------------------------
extern "C" void kernel_launch(void* const* d_in, const int* in_sizes, int n_in,
                              void* d_out, int out_size)
{
    const float* x     = (const float*)d_in[0];
    const float* w_in  = (const float*)d_in[1];
    const float* b_in  = (const float*)d_in[2];
    const float* w_out = (const float*)d_in[3];
    const float* b_out = (const float*)d_in[4];
    float* out = (float*)d_out;

    static float* qkv_buf  = nullptr;
    static float* attn_buf = nullptr;
    static bool   init     = false;
    if (!init) {
        cudaGetSymbolAddress((void**)&qkv_buf,  g_qkv);
        cudaGetSymbolAddress((void**)&attn_buf, g_attn);
        cudaFuncSetAttribute(mha_attn_kernel,
                             cudaFuncAttributeMaxDynamicSharedMemorySize,
                             ATTN_SMEM_BYTES);
        init = true;
    }

    // 1) QKV projection: [4096,1024] @ [1024,3072] + b_in
    sgemm_bias_128x128<<<dim3(3 * EMB / 128, NTOK / 128), 256>>>(
        x, w_in, b_in, qkv_buf, NTOK, 3 * EMB, EMB);

    // 2) Attention per (batch, head), 128-query tiles
    mha_attn_kernel<<<dim3(SEQ / 128, BATCH * NH), 128, ATTN_SMEM_BYTES>>>(
        qkv_buf, attn_buf);

    // 3) Output projection: [4096,1024] @ [1024,1024] + b_out
    sgemm_bias_128x128<<<dim3(EMB / 128, NTOK / 128), 256>>>(
        attn_buf, w_out, b_out, out, NTOK, EMB, EMB);
}